// round 15
// baseline (speedup 1.0000x reference)
#include <cuda_runtime.h>
#include <cuda_fp16.h>
#include <math.h>
#include <stdint.h>

#define Bb 128
#define Ll 512
#define Dd 300
#define Hh 200
#define Vv 50000

#define KPAD 320        // Dd padded to 32
#define NPADW 224       // Hh padded to 224 (= 4 warps * 56)
#define NPREPA 1250     // prepA blocks in k_pre

// Scratch (device globals -- no allocation allowed)
__device__ __half g_Wh[NPADW * KPAD];        // fp16 W1_top^T, n-major, zero-padded
__device__ __half g_Eh[Vv * KPAD];           // fp16 padded emb table (32 MB)
__device__ float  g_subj_part[Bb * 8 * Dd];
__device__ float  g_obj_part[Bb * 8 * Dd];
__device__ float  g_subj[Bb * Dd];
__device__ float  g_obj[Bb * Dd];
__device__ float  g_sup_part[Bb * 6 * Hh];   // sup-projection K partials
__device__ float  g_score[Bb * Ll];
__device__ float  g_attn_part[Bb * 16 * Dd];
__device__ float  g_hid_part[Bb * 8 * Hh];   // mlp layer-1 K partials

__device__ __forceinline__ void cp16(uint32_t dst, const void* src) {
    asm volatile("cp.async.cg.shared.global [%0], [%1], 16;\n"
                 :: "r"(dst), "l"(src));
}

// ---------------------------------------------------------------------------
// Kernel 1 (merged): blocks [0, B*8): partial masked max-pools (fp32 emb);
// blocks [B*8, B*8+70): W1_top -> g_Wh; blocks [B*8+70, ...): emb -> g_Eh.
// block = 320
// ---------------------------------------------------------------------------
__global__ void k_pre(const int* __restrict__ words,
                      const int* __restrict__ spos,
                      const int* __restrict__ opos,
                      const float* __restrict__ emb,
                      const float* __restrict__ w1) {
    int bx = blockIdx.x;
    int tid = threadIdx.x;
    if (bx >= Bb * 8 + 70) {
        // --- prepA: emb f32 -> padded f16 image g_Eh ---
        int idx = (bx - (Bb * 8 + 70)) * 320 + tid;     // half2 index
        const int total = Vv * (KPAD / 2);
        for (; idx < total; idx += NPREPA * 320) {
            int row = idx / (KPAD / 2);
            int c2 = idx % (KPAD / 2);
            __half2 v = __float2half2_rn(0.f);
            if (c2 < Dd / 2) {
                const float* p = emb + (long)row * Dd + 2 * c2;
                v = __floats2half2_rn(p[0], p[1]);
            }
            reinterpret_cast<__half2*>(g_Eh)[(long)row * (KPAD / 2) + c2] = v;
        }
        return;
    }
    if (bx >= Bb * 8) {
        // --- prepW ---
        int idx = (bx - Bb * 8) * 320 + tid;
        int total = NPADW * KPAD;
        for (; idx < total; idx += 70 * 320) {
            int n = idx / KPAD;
            int k = idx % KPAD;
            float v = (n < Hh && k < Dd) ? w1[k * Hh + n] : 0.f;
            g_Wh[idx] = __float2half(v);
        }
        return;
    }
    // --- pools ---
    int b = bx >> 3, ch = bx & 7;
    __shared__ int sl[64], ol[64];
    __shared__ int scnt, ocnt;
    if (tid == 0) { scnt = 0; ocnt = 0; }
    __syncthreads();
    int base = b * Ll + ch * 64;
    if (tid < 64) {
        int w = words[base + tid];
        if (spos[base + tid] == 0) sl[atomicAdd(&scnt, 1)] = w;
        if (opos[base + tid] == 0) ol[atomicAdd(&ocnt, 1)] = w;
    }
    __syncthreads();
    int ns = scnt, no = ocnt;
    if (tid < Dd) {
        float smax = -1e12f, omax = -1e12f;
        for (int i = 0; i < ns; i++)
            smax = fmaxf(smax, emb[(long)sl[i] * Dd + tid]);
        for (int i = 0; i < no; i++)
            omax = fmaxf(omax, emb[(long)ol[i] * Dd + tid]);
        g_subj_part[(b * 8 + ch) * Dd + tid] = smax;
        g_obj_part[(b * 8 + ch) * Dd + tid]  = omax;
    }
}

// ---------------------------------------------------------------------------
// Kernel 1b (merged fin+sup): grid (B, 6), block 320.
// ---------------------------------------------------------------------------
__global__ void k_fin_sup(const float* __restrict__ w1) {
    int b = blockIdx.x, kc = blockIdx.y;
    int tid = threadIdx.x;
    __shared__ float ssub[Dd];
    if (tid < Dd) {
        float s = -1e12f;
        #pragma unroll
        for (int c = 0; c < 8; c++)
            s = fmaxf(s, g_subj_part[(b * 8 + c) * Dd + tid]);
        ssub[tid] = s;
        if (kc == 0) {
            g_subj[b * Dd + tid] = s;
            float o = -1e12f;
            #pragma unroll
            for (int c = 0; c < 8; c++)
                o = fmaxf(o, g_obj_part[(b * 8 + c) * Dd + tid]);
            g_obj[b * Dd + tid] = o;
        }
    }
    __syncthreads();
    if (tid < Hh) {
        float acc = 0.f;
        const float* sp = ssub + kc * 50;
        const float* wp = w1 + (Dd + kc * 50) * Hh + tid;
        #pragma unroll 10
        for (int i = 0; i < 50; i++)
            acc += sp[i] * wp[i * Hh];
        g_sup_part[(b * 6 + kc) * Hh + tid] = acc;
    }
}

// ---------------------------------------------------------------------------
// Kernel 2 (FUSED): per 64-token tile, gather fp16 emb rows (cp.async,
// 4-stage pipeline, unguarded), fp16 mma.sync m16n8k16 vs W1_top^T, then
// score[tok] = b2 + sum_n w2[n]*tanh(hid[tok,n]+sup[b,n]).
// grid (B, 8), 256 threads, 8 warps as 2(m) x 4(n), warp tile 32x56.
// 94.5 KB smem -> 2 CTAs/SM.
// ---------------------------------------------------------------------------
#define FSM_A    0              // half A[4][64][40]   = 20480
#define FSM_B    20480          // half B[4][224][40]  = 71680
#define FSM_WD   92160          // int  wds[64]        = 256
#define FSM_SUP  92416          // float sup[224]      = 896
#define FSM_W2   93312          // float w2s[224]      = 896
#define FSM_SC   94208          // float sc[64]        = 256
#define FSM_TOTAL 94464

__global__ void __launch_bounds__(256) k_fused(const int* __restrict__ words,
                                               const float* __restrict__ w2,
                                               const float* __restrict__ b2,
                                               const float* __restrict__ b1) {
    extern __shared__ char sm[];
    uint32_t smBase;
    asm("{ .reg .u64 t; cvta.to.shared.u64 t, %1; cvt.u32.u64 %0, t; }"
        : "=r"(smBase) : "l"(sm));

    __half* Ah = (__half*)(sm + FSM_A);       // [4][64][40]
    __half* Bh = (__half*)(sm + FSM_B);       // [4][224][40]
    int*   wds = (int*)(sm + FSM_WD);
    float* sup = (float*)(sm + FSM_SUP);
    float* w2s = (float*)(sm + FSM_W2);
    float* sc  = (float*)(sm + FSM_SC);

    int b = blockIdx.x, ch = blockIdx.y;
    int tid = threadIdx.x;
    int wid = tid >> 5;
    int lane = tid & 31;
    int g = lane >> 2, t = lane & 3;
    int warp_m = wid >> 2;                    // 0..1
    int warp_n = wid & 3;                     // 0..3

    float bias = b2[0];
    if (tid < 64) {
        wds[tid] = words[b * Ll + ch * 64 + tid];
        sc[tid] = bias;
    }
    if (tid < NPADW) {
        if (tid < Hh) {
            float s = b1[tid];
            #pragma unroll
            for (int c = 0; c < 6; c++)
                s += g_sup_part[(b * 6 + c) * Hh + tid];
            sup[tid] = s;
            w2s[tid] = w2[tid];
        } else {
            sup[tid] = 0.f;
            w2s[tid] = 0.f;
        }
    }
    __syncthreads();

    int arow = tid >> 2;                      // 0..63
    int aseg = tid & 3;                       // 16B segment (8 halves)
    const __half* rowsrc = g_Eh + (long)wds[arow] * KPAD;

    #define F_LOAD(buf, c)                                                    \
    {                                                                         \
        {                                                                     \
            uint32_t dst = smBase + FSM_A +                                   \
                (uint32_t)((buf) * 2560 + arow * 40 + aseg * 8) * 2u;         \
            cp16(dst, rowsrc + (c) * 32 + aseg * 8);                          \
        }                                                                     \
        _Pragma("unroll")                                                     \
        for (int p = 0; p < 4; p++) {                                         \
            int idx = tid + p * 256;                                          \
            if (idx < 896) {                                                  \
                int r = idx >> 2, sg = idx & 3;                               \
                uint32_t dst = smBase + FSM_B +                               \
                    (uint32_t)((buf) * 8960 + r * 40 + sg * 8) * 2u;          \
                cp16(dst, g_Wh + r * KPAD + (c) * 32 + sg * 8);               \
            }                                                                 \
        }                                                                     \
        asm volatile("cp.async.commit_group;");                               \
    }

    float acc[2][7][4];
    #pragma unroll
    for (int i = 0; i < 2; i++)
        #pragma unroll
        for (int j = 0; j < 7; j++)
            #pragma unroll
            for (int c = 0; c < 4; c++) acc[i][j][c] = 0.f;

    F_LOAD(0, 0);
    F_LOAD(1, 1);
    F_LOAD(2, 2);

    const int NIT = KPAD / 32;                // 10
    for (int it = 0; it < NIT; it++) {
        // committed groups so far: chunks 0..min(NIT-1, it+2)
        if (it < NIT - 2)
            asm volatile("cp.async.wait_group 2;");
        else
            asm volatile("cp.async.wait_group 0;");
        __syncthreads();
        if (it + 3 < NIT) F_LOAD((it + 3) & 3, it + 3);
        int buf = it & 3;
        const __half* Afb = Ah + buf * 2560;
        const __half* Bhb = Bh + buf * 8960;

        #pragma unroll
        for (int ks = 0; ks < 2; ks++) {
            int kl = ks * 16;
            uint32_t ua[2][4], ub[7][2];
            #pragma unroll
            for (int mt = 0; mt < 2; mt++) {
                int mr = warp_m * 32 + mt * 16;
                const __half* r1 = Afb + (mr + g) * 40 + kl + 2 * t;
                const __half* r2 = Afb + (mr + g + 8) * 40 + kl + 2 * t;
                ua[mt][0] = *(const uint32_t*)r1;
                ua[mt][1] = *(const uint32_t*)r2;
                ua[mt][2] = *(const uint32_t*)(r1 + 8);
                ua[mt][3] = *(const uint32_t*)(r2 + 8);
            }
            #pragma unroll
            for (int nt = 0; nt < 7; nt++) {
                int nc = warp_n * 56 + nt * 8;
                ub[nt][0] = *(const uint32_t*)&Bhb[(nc + g) * 40 + kl + 2 * t];
                ub[nt][1] = *(const uint32_t*)&Bhb[(nc + g) * 40 + kl + 2 * t + 8];
            }
            #pragma unroll
            for (int mt = 0; mt < 2; mt++)
                #pragma unroll
                for (int nt = 0; nt < 7; nt++)
                    asm volatile(
                        "mma.sync.aligned.m16n8k16.row.col.f32.f16.f16.f32 "
                        "{%0,%1,%2,%3}, {%4,%5,%6,%7}, {%8,%9}, {%0,%1,%2,%3};"
                        : "+f"(acc[mt][nt][0]), "+f"(acc[mt][nt][1]),
                          "+f"(acc[mt][nt][2]), "+f"(acc[mt][nt][3])
                        : "r"(ua[mt][0]), "r"(ua[mt][1]), "r"(ua[mt][2]), "r"(ua[mt][3]),
                          "r"(ub[nt][0]), "r"(ub[nt][1]));
        }
    }
    __syncthreads();

    // epilogue: score contributions; shfl-reduce over t (lanes g*4 + 0..3)
    #pragma unroll
    for (int mt = 0; mt < 2; mt++) {
        int r1 = warp_m * 32 + mt * 16 + g;
        float rs0 = 0.f, rs1 = 0.f;
        #pragma unroll
        for (int nt = 0; nt < 7; nt++) {
            int col = warp_n * 56 + nt * 8 + 2 * t;
            float wa = w2s[col], wb = w2s[col + 1];
            float sa = sup[col], sb = sup[col + 1];
            float t0, t1, t2, t3;
            asm("tanh.approx.f32 %0, %1;" : "=f"(t0) : "f"(acc[mt][nt][0] + sa));
            asm("tanh.approx.f32 %0, %1;" : "=f"(t1) : "f"(acc[mt][nt][1] + sb));
            asm("tanh.approx.f32 %0, %1;" : "=f"(t2) : "f"(acc[mt][nt][2] + sa));
            asm("tanh.approx.f32 %0, %1;" : "=f"(t3) : "f"(acc[mt][nt][3] + sb));
            rs0 += wa * t0 + wb * t1;
            rs1 += wa * t2 + wb * t3;
        }
        rs0 += __shfl_xor_sync(0xffffffffu, rs0, 1);
        rs0 += __shfl_xor_sync(0xffffffffu, rs0, 2);
        rs1 += __shfl_xor_sync(0xffffffffu, rs1, 1);
        rs1 += __shfl_xor_sync(0xffffffffu, rs1, 2);
        if (t == 0) {
            atomicAdd(&sc[r1], rs0);
            atomicAdd(&sc[r1 + 8], rs1);
        }
    }
    __syncthreads();
    if (tid < 64)
        g_score[b * Ll + ch * 64 + tid] = sc[tid];
}

// ---------------------------------------------------------------------------
// Kernel 4 (softmax fused): grid (B,8), block 640 = 2 groups of 320.
// Gathers from the fp16 emb image (L2-resident).
// ---------------------------------------------------------------------------
__global__ void k_attn_part(const int* __restrict__ words) {
    int b = blockIdx.x, ch = blockIdx.y;
    int tid = threadIdx.x;
    __shared__ float red[512];
    __shared__ float p[64];
    __shared__ int sw[64];
    float scv = 0.f;
    if (tid < 512) {
        scv = g_score[b * Ll + tid];
        red[tid] = scv;
    }
    __syncthreads();
    for (int s = 256; s > 0; s >>= 1) {
        if (tid < s) red[tid] = fmaxf(red[tid], red[tid + s]);
        __syncthreads();
    }
    float m = red[0];
    __syncthreads();
    if (tid < 512) red[tid] = expf(scv - m);
    __syncthreads();
    for (int s = 256; s > 0; s >>= 1) {
        if (tid < s) red[tid] += red[tid + s];
        __syncthreads();
    }
    float inv = 1.f / red[0];
    int base = b * Ll + ch * 64;
    if (tid < 64) {
        p[tid] = expf(g_score[base + tid] - m) * inv;
        sw[tid] = words[base + tid];
    }
    __syncthreads();
    int grp = tid / 320;                 // 0 or 1
    int d = tid - grp * 320;             // 0..319
    if (d < Dd) {
        float acc = 0.f;
        int i0 = grp * 32;
        #pragma unroll 8
        for (int i = 0; i < 32; i++)
            acc += p[i0 + i] * __half2float(g_Eh[(long)sw[i0 + i] * KPAD + d]);
        g_attn_part[(b * 16 + ch * 2 + grp) * Dd + d] = acc;
    }
}

// ---------------------------------------------------------------------------
// Kernel 5a: MLP layer-1 K partials. grid (B, 8), block 256, chunks of 150.
// ---------------------------------------------------------------------------
__global__ void k_mlp1(const float* __restrict__ mw1) {
    int b = blockIdx.x, kc = blockIdx.y;
    int seg = kc >> 1, half = kc & 1;
    int tid = threadIdx.x;
    __shared__ float v[152];
    if (tid < 150) {
        int i = half * 150 + tid;
        float a;
        if (seg <= 1) {
            a = 0.f;
            #pragma unroll
            for (int c = 0; c < 16; c++)
                a += g_attn_part[(b * 16 + c) * Dd + i];
        } else if (seg == 2) {
            a = g_subj[b * Dd + i];
        } else {
            a = g_obj[b * Dd + i];
        }
        v[tid] = a;
    }
    __syncthreads();
    if (tid < Hh) {
        float acc = 0.f;
        const float* wp = mw1 + (seg * Dd + half * 150) * Hh + tid;
        #pragma unroll 10
        for (int i = 0; i < 150; i++)
            acc += v[i] * wp[i * Hh];
        g_hid_part[(b * 8 + kc) * Hh + tid] = acc;
    }
}

// ---------------------------------------------------------------------------
// Kernel 5b: combine partials + relu, then layer 2. grid = B, block 256.
// ---------------------------------------------------------------------------
__global__ void k_mlp2(const float* __restrict__ mb1,
                       const float* __restrict__ mw2,
                       const float* __restrict__ mb2,
                       float* __restrict__ out) {
    int b = blockIdx.x;
    int tid = threadIdx.x;
    __shared__ float hid[Hh];
    if (tid < Hh) {
        float a = mb1[tid];
        #pragma unroll
        for (int c = 0; c < 8; c++)
            a += g_hid_part[(b * 8 + c) * Hh + tid];
        hid[tid] = fmaxf(a, 0.f);
    }
    __syncthreads();
    if (tid < Hh) {
        float a = mb2[tid];
        const float* wp = mw2 + tid;
        #pragma unroll 10
        for (int k = 0; k < Hh; k++)
            a += hid[k] * wp[k * Hh];
        out[b * Hh + tid] = fmaxf(a, 0.f);
    }
}

// ---------------------------------------------------------------------------
extern "C" void kernel_launch(void* const* d_in, const int* in_sizes, int n_in,
                              void* d_out, int out_size) {
    const int*   words = (const int*)d_in[0];
    const int*   spos  = (const int*)d_in[1];
    const int*   opos  = (const int*)d_in[2];
    const float* emb   = (const float*)d_in[3];
    const float* w1    = (const float*)d_in[4];
    const float* b1    = (const float*)d_in[5];
    const float* w2    = (const float*)d_in[6];
    const float* b2    = (const float*)d_in[7];
    const float* mw1   = (const float*)d_in[8];
    const float* mb1   = (const float*)d_in[9];
    const float* mw2   = (const float*)d_in[10];
    const float* mb2   = (const float*)d_in[11];
    float* out = (float*)d_out;

    cudaFuncSetAttribute(k_fused, cudaFuncAttributeMaxDynamicSharedMemorySize,
                         FSM_TOTAL);

    k_pre<<<Bb * 8 + 70 + NPREPA, 320>>>(words, spos, opos, emb, w1);
    k_fin_sup<<<dim3(Bb, 6), 320>>>(w1);
    k_fused<<<dim3(Bb, 8), 256, FSM_TOTAL>>>(words, w2, b2, b1);
    k_attn_part<<<dim3(Bb, 8), 640>>>(words);
    k_mlp1<<<dim3(Bb, 8), 256>>>(mw1);
    k_mlp2<<<Bb, 256>>>(mb1, mw2, mb2, out);
}

// round 16
// speedup vs baseline: 1.1393x; 1.1393x over previous
#include <cuda_runtime.h>
#include <cuda_fp16.h>
#include <math.h>
#include <stdint.h>

#define Bb 128
#define Ll 512
#define Dd 300
#define Hh 200
#define Vv 50000

#define KPAD 320        // Dd padded to 32
#define NPADW 224       // Hh padded to 224 (= 4 warps * 56)

// Scratch (device globals -- no allocation allowed)
__device__ __half g_Wh[NPADW * KPAD];        // fp16 W1_top^T, n-major, zero-padded
__device__ float  g_subj_part[Bb * 8 * Dd];
__device__ float  g_obj_part[Bb * 8 * Dd];
__device__ float  g_subj[Bb * Dd];
__device__ float  g_obj[Bb * Dd];
__device__ float  g_sup_part[Bb * 6 * Hh];   // sup-projection K partials
__device__ float  g_score[Bb * Ll];
__device__ float  g_attn_part[Bb * 8 * Dd];
__device__ float  g_hid_part[Bb * 8 * Hh];   // mlp layer-1 K partials

__device__ __forceinline__ void cp16(uint32_t dst, const void* src) {
    asm volatile("cp.async.cg.shared.global [%0], [%1], 16;\n"
                 :: "r"(dst), "l"(src));
}
__device__ __forceinline__ void cp16p(uint32_t dst, const void* src, bool v) {
    asm volatile("cp.async.cg.shared.global [%0], [%1], 16, %2;\n"
                 :: "r"(dst), "l"(src), "r"(v ? 16 : 0));
}
__device__ __forceinline__ uint32_t pkh2(float a, float b) {
    __half2 h = __floats2half2_rn(a, b);
    return *reinterpret_cast<uint32_t*>(&h);
}

// ---------------------------------------------------------------------------
// Kernel 1 (merged): blocks [0, B*8): partial masked max-pools over 64
// positions; blocks [B*8, B*8+70): W1_top f32 -> transposed f16 image g_Wh.
// block = 320
// ---------------------------------------------------------------------------
__global__ void k_pre(const int* __restrict__ words,
                      const int* __restrict__ spos,
                      const int* __restrict__ opos,
                      const float* __restrict__ emb,
                      const float* __restrict__ w1) {
    int bx = blockIdx.x;
    int tid = threadIdx.x;
    if (bx >= Bb * 8) {
        int idx = (bx - Bb * 8) * 320 + tid;
        int total = NPADW * KPAD;
        for (; idx < total; idx += 70 * 320) {
            int n = idx / KPAD;
            int k = idx % KPAD;
            float v = (n < Hh && k < Dd) ? w1[k * Hh + n] : 0.f;
            g_Wh[idx] = __float2half(v);
        }
        return;
    }
    int b = bx >> 3, ch = bx & 7;
    __shared__ int sl[64], ol[64];
    __shared__ int scnt, ocnt;
    if (tid == 0) { scnt = 0; ocnt = 0; }
    __syncthreads();
    int base = b * Ll + ch * 64;
    if (tid < 64) {
        int w = words[base + tid];
        if (spos[base + tid] == 0) sl[atomicAdd(&scnt, 1)] = w;
        if (opos[base + tid] == 0) ol[atomicAdd(&ocnt, 1)] = w;
    }
    __syncthreads();
    int ns = scnt, no = ocnt;
    if (tid < Dd) {
        float smax = -1e12f, omax = -1e12f;
        for (int i = 0; i < ns; i++)
            smax = fmaxf(smax, emb[(long)sl[i] * Dd + tid]);
        for (int i = 0; i < no; i++)
            omax = fmaxf(omax, emb[(long)ol[i] * Dd + tid]);
        g_subj_part[(b * 8 + ch) * Dd + tid] = smax;
        g_obj_part[(b * 8 + ch) * Dd + tid]  = omax;
    }
}

// ---------------------------------------------------------------------------
// Kernel 1b: combine partial maxes. grid = B, block = 320
// ---------------------------------------------------------------------------
__global__ void k_pools_fin() {
    int b = blockIdx.x;
    int tid = threadIdx.x;
    if (tid < Dd) {
        float s = -1e12f, o = -1e12f;
        #pragma unroll
        for (int c = 0; c < 8; c++) {
            s = fmaxf(s, g_subj_part[(b * 8 + c) * Dd + tid]);
            o = fmaxf(o, g_obj_part[(b * 8 + c) * Dd + tid]);
        }
        g_subj[b * Dd + tid] = s;
        g_obj[b * Dd + tid]  = o;
    }
}

// ---------------------------------------------------------------------------
// Kernel 1c: sup-projection K partials. grid (B, 6), block 256.
// ---------------------------------------------------------------------------
__global__ void k_supproj(const float* __restrict__ w1) {
    int b = blockIdx.x, kc = blockIdx.y;
    int tid = threadIdx.x;
    __shared__ float ssub[56];
    if (tid < 50) ssub[tid] = g_subj[b * Dd + kc * 50 + tid];
    __syncthreads();
    if (tid < Hh) {
        float acc = 0.f;
        const float* wp = w1 + (Dd + kc * 50) * Hh + tid;
        #pragma unroll 10
        for (int i = 0; i < 50; i++)
            acc += ssub[i] * wp[i * Hh];
        g_sup_part[(b * 6 + kc) * Hh + tid] = acc;
    }
}

// ---------------------------------------------------------------------------
// Kernel 2 (FUSED): per 64-token tile, gather emb rows (fp32, cp.async,
// 3-stage pipeline), fp16 mma.sync m16n8k16 vs W1_top^T, then
// score[tok] = b2 + sum_n w2[n]*tanh(hid[tok,n]+sup[b,n]).
// grid (B, 8), 256 threads, 8 warps as 2(m) x 4(n), warp tile 32x56.
// 2 CTAs/SM (83.7 KB smem each) for cross-CTA latency hiding.
// ---------------------------------------------------------------------------
#define FSM_A    0              // float A[3][64][36]  = 27648
#define FSM_B    27648          // half  B[3][224][40] = 53760
#define FSM_WD   81408          // int   wds[64]       = 256
#define FSM_SUP  81664          // float sup[224]      = 896
#define FSM_W2   82560          // float w2s[224]      = 896
#define FSM_SC   83456          // float sc[64]        = 256
#define FSM_TOTAL 83712

__global__ void __launch_bounds__(256) k_fused(const int* __restrict__ words,
                                               const float* __restrict__ emb,
                                               const float* __restrict__ w2,
                                               const float* __restrict__ b2,
                                               const float* __restrict__ b1) {
    extern __shared__ char sm[];
    uint32_t smBase;
    asm("{ .reg .u64 t; cvta.to.shared.u64 t, %1; cvt.u32.u64 %0, t; }"
        : "=r"(smBase) : "l"(sm));

    float* Af  = (float*)(sm + FSM_A);        // [3][64][36]
    __half* Bh = (__half*)(sm + FSM_B);       // [3][224][40]
    int*   wds = (int*)(sm + FSM_WD);
    float* sup = (float*)(sm + FSM_SUP);
    float* w2s = (float*)(sm + FSM_W2);
    float* sc  = (float*)(sm + FSM_SC);

    int b = blockIdx.x, ch = blockIdx.y;
    int tid = threadIdx.x;
    int wid = tid >> 5;
    int lane = tid & 31;
    int g = lane >> 2, t = lane & 3;
    int warp_m = wid >> 2;                    // 0..1
    int warp_n = wid & 3;                     // 0..3

    float bias = b2[0];
    if (tid < 64) {
        wds[tid] = words[b * Ll + ch * 64 + tid];
        sc[tid] = bias;
    }
    if (tid < NPADW) {
        if (tid < Hh) {
            float s = b1[tid];
            #pragma unroll
            for (int c = 0; c < 6; c++)
                s += g_sup_part[(b * 6 + c) * Hh + tid];
            sup[tid] = s;
            w2s[tid] = w2[tid];
        } else {
            sup[tid] = 0.f;
            w2s[tid] = 0.f;
        }
    }
    __syncthreads();

    int arow = tid >> 2;                      // 0..63
    int s0 = tid & 3;                         // segments s0, s0+4
    const float* rowsrc = emb + (long)wds[arow] * Dd;

    #define F_LOAD(buf, c)                                                    \
    {                                                                         \
        int kb = (c) * 32;                                                    \
        _Pragma("unroll")                                                     \
        for (int s = 0; s < 2; s++) {                                         \
            int seg = s0 + s * 4;                                             \
            bool v = (kb + seg * 4 + 4 <= Dd);                                \
            uint32_t dst = smBase + FSM_A +                                   \
                (uint32_t)((buf) * 2304 + arow * 36 + seg * 4) * 4u;          \
            cp16p(dst, rowsrc + kb + seg * 4, v);                             \
        }                                                                     \
        _Pragma("unroll")                                                     \
        for (int p = 0; p < 4; p++) {                                         \
            int idx = tid + p * 256;                                          \
            if (idx < 896) {                                                  \
                int r = idx >> 2, sg = idx & 3;                               \
                uint32_t dst = smBase + FSM_B +                               \
                    (uint32_t)((buf) * 8960 + r * 40 + sg * 8) * 2u;          \
                cp16(dst, g_Wh + r * KPAD + (c) * 32 + sg * 8);               \
            }                                                                 \
        }                                                                     \
        asm volatile("cp.async.commit_group;");                               \
    }

    float acc[2][7][4];
    #pragma unroll
    for (int i = 0; i < 2; i++)
        #pragma unroll
        for (int j = 0; j < 7; j++)
            #pragma unroll
            for (int c = 0; c < 4; c++) acc[i][j][c] = 0.f;

    F_LOAD(0, 0);
    F_LOAD(1, 1);

    const int NIT = KPAD / 32;                // 10
    for (int it = 0; it < NIT; it++) {
        asm volatile("cp.async.wait_group 1;");
        __syncthreads();
        {
            int nxt = it + 2;
            if (nxt < NIT) {
                int nb = nxt - (nxt / 3) * 3;
                F_LOAD(nb, nxt);
            }
        }
        int buf = it - (it / 3) * 3;
        const float* Afb = Af + buf * 2304;
        const __half* Bhb = Bh + buf * 8960;

        #pragma unroll
        for (int ks = 0; ks < 2; ks++) {
            int kl = ks * 16;
            uint32_t ua[2][4], ub[7][2];
            #pragma unroll
            for (int mt = 0; mt < 2; mt++) {
                int mr = warp_m * 32 + mt * 16;
                const float* r1 = Afb + (mr + g) * 36 + kl + 2 * t;
                const float* r2 = Afb + (mr + g + 8) * 36 + kl + 2 * t;
                ua[mt][0] = pkh2(r1[0], r1[1]);
                ua[mt][1] = pkh2(r2[0], r2[1]);
                ua[mt][2] = pkh2(r1[8], r1[9]);
                ua[mt][3] = pkh2(r2[8], r2[9]);
            }
            #pragma unroll
            for (int nt = 0; nt < 7; nt++) {
                int nc = warp_n * 56 + nt * 8;
                ub[nt][0] = *(const uint32_t*)&Bhb[(nc + g) * 40 + kl + 2 * t];
                ub[nt][1] = *(const uint32_t*)&Bhb[(nc + g) * 40 + kl + 2 * t + 8];
            }
            #pragma unroll
            for (int mt = 0; mt < 2; mt++)
                #pragma unroll
                for (int nt = 0; nt < 7; nt++)
                    asm volatile(
                        "mma.sync.aligned.m16n8k16.row.col.f32.f16.f16.f32 "
                        "{%0,%1,%2,%3}, {%4,%5,%6,%7}, {%8,%9}, {%0,%1,%2,%3};"
                        : "+f"(acc[mt][nt][0]), "+f"(acc[mt][nt][1]),
                          "+f"(acc[mt][nt][2]), "+f"(acc[mt][nt][3])
                        : "r"(ua[mt][0]), "r"(ua[mt][1]), "r"(ua[mt][2]), "r"(ua[mt][3]),
                          "r"(ub[nt][0]), "r"(ub[nt][1]));
        }
    }
    __syncthreads();

    // epilogue: score contributions; shfl-reduce over t (lanes g*4 + 0..3)
    #pragma unroll
    for (int mt = 0; mt < 2; mt++) {
        int r1 = warp_m * 32 + mt * 16 + g;
        float rs0 = 0.f, rs1 = 0.f;
        #pragma unroll
        for (int nt = 0; nt < 7; nt++) {
            int col = warp_n * 56 + nt * 8 + 2 * t;
            float wa = w2s[col], wb = w2s[col + 1];
            float sa = sup[col], sb = sup[col + 1];
            float t0, t1, t2, t3;
            asm("tanh.approx.f32 %0, %1;" : "=f"(t0) : "f"(acc[mt][nt][0] + sa));
            asm("tanh.approx.f32 %0, %1;" : "=f"(t1) : "f"(acc[mt][nt][1] + sb));
            asm("tanh.approx.f32 %0, %1;" : "=f"(t2) : "f"(acc[mt][nt][2] + sa));
            asm("tanh.approx.f32 %0, %1;" : "=f"(t3) : "f"(acc[mt][nt][3] + sb));
            rs0 += wa * t0 + wb * t1;
            rs1 += wa * t2 + wb * t3;
        }
        rs0 += __shfl_xor_sync(0xffffffffu, rs0, 1);
        rs0 += __shfl_xor_sync(0xffffffffu, rs0, 2);
        rs1 += __shfl_xor_sync(0xffffffffu, rs1, 1);
        rs1 += __shfl_xor_sync(0xffffffffu, rs1, 2);
        if (t == 0) {
            atomicAdd(&sc[r1], rs0);
            atomicAdd(&sc[r1 + 8], rs1);
        }
    }
    __syncthreads();
    if (tid < 64)
        g_score[b * Ll + ch * 64 + tid] = sc[tid];
}

// ---------------------------------------------------------------------------
// Kernel 4 (softmax fused): grid (B,8), block 640 = 4 groups of 160.
// Softmax redone per block; group grp covers 16 of the block's 64 positions;
// each thread accumulates a float2 over dims (2d2, 2d2+1). Group partials are
// combined in smem -> one write per (b,ch), keeping g_attn_part at 8 slots.
// ---------------------------------------------------------------------------
__global__ void k_attn_part(const int* __restrict__ words,
                            const float* __restrict__ emb) {
    int b = blockIdx.x, ch = blockIdx.y;
    int tid = threadIdx.x;
    __shared__ float red[512];
    __shared__ float p[64];
    __shared__ int sw[64];
    __shared__ float part[4][Dd];
    float scv = 0.f;
    if (tid < 512) {
        scv = g_score[b * Ll + tid];
        red[tid] = scv;
    }
    __syncthreads();
    for (int s = 256; s > 0; s >>= 1) {
        if (tid < s) red[tid] = fmaxf(red[tid], red[tid + s]);
        __syncthreads();
    }
    float m = red[0];
    __syncthreads();
    if (tid < 512) red[tid] = expf(scv - m);
    __syncthreads();
    for (int s = 256; s > 0; s >>= 1) {
        if (tid < s) red[tid] += red[tid + s];
        __syncthreads();
    }
    float inv = 1.f / red[0];
    int base = b * Ll + ch * 64;
    if (tid < 64) {
        p[tid] = expf(g_score[base + tid] - m) * inv;
        sw[tid] = words[base + tid];
    }
    __syncthreads();
    int grp = tid / 160;                 // 0..3
    int d2 = tid - grp * 160;            // 0..159
    if (d2 < 150) {
        float a0 = 0.f, a1 = 0.f;
        int i0 = grp * 16;
        #pragma unroll 16
        for (int i = 0; i < 16; i++) {
            float2 e = *reinterpret_cast<const float2*>(
                emb + (long)sw[i0 + i] * Dd + 2 * d2);
            float w = p[i0 + i];
            a0 += w * e.x;
            a1 += w * e.y;
        }
        part[grp][2 * d2]     = a0;
        part[grp][2 * d2 + 1] = a1;
    }
    __syncthreads();
    if (tid < Dd) {
        float a = part[0][tid] + part[1][tid] + part[2][tid] + part[3][tid];
        g_attn_part[(b * 8 + ch) * Dd + tid] = a;
    }
}

// ---------------------------------------------------------------------------
// Kernel 5a: MLP layer-1 K partials. grid (B, 8), block 256, chunks of 150.
// feat segment seg = kc/2 (0/1: attn; 2: subj; 3: obj), half = kc&1.
// ---------------------------------------------------------------------------
__global__ void k_mlp1(const float* __restrict__ mw1) {
    int b = blockIdx.x, kc = blockIdx.y;
    int seg = kc >> 1, half = kc & 1;
    int tid = threadIdx.x;
    __shared__ float v[152];
    if (tid < 150) {
        int i = half * 150 + tid;
        float a;
        if (seg <= 1) {
            a = 0.f;
            #pragma unroll
            for (int c = 0; c < 8; c++)
                a += g_attn_part[(b * 8 + c) * Dd + i];
        } else if (seg == 2) {
            a = g_subj[b * Dd + i];
        } else {
            a = g_obj[b * Dd + i];
        }
        v[tid] = a;
    }
    __syncthreads();
    if (tid < Hh) {
        float acc = 0.f;
        const float* wp = mw1 + (seg * Dd + half * 150) * Hh + tid;
        #pragma unroll 10
        for (int i = 0; i < 150; i++)
            acc += v[i] * wp[i * Hh];
        g_hid_part[(b * 8 + kc) * Hh + tid] = acc;
    }
}

// ---------------------------------------------------------------------------
// Kernel 5b: combine partials + relu, then layer 2. grid = B, block 256.
// ---------------------------------------------------------------------------
__global__ void k_mlp2(const float* __restrict__ mb1,
                       const float* __restrict__ mw2,
                       const float* __restrict__ mb2,
                       float* __restrict__ out) {
    int b = blockIdx.x;
    int tid = threadIdx.x;
    __shared__ float hid[Hh];
    if (tid < Hh) {
        float a = mb1[tid];
        #pragma unroll
        for (int c = 0; c < 8; c++)
            a += g_hid_part[(b * 8 + c) * Hh + tid];
        hid[tid] = fmaxf(a, 0.f);
    }
    __syncthreads();
    if (tid < Hh) {
        float a = mb2[tid];
        const float* wp = mw2 + tid;
        #pragma unroll 10
        for (int k = 0; k < Hh; k++)
            a += hid[k] * wp[k * Hh];
        out[b * Hh + tid] = fmaxf(a, 0.f);
    }
}

// ---------------------------------------------------------------------------
extern "C" void kernel_launch(void* const* d_in, const int* in_sizes, int n_in,
                              void* d_out, int out_size) {
    const int*   words = (const int*)d_in[0];
    const int*   spos  = (const int*)d_in[1];
    const int*   opos  = (const int*)d_in[2];
    const float* emb   = (const float*)d_in[3];
    const float* w1    = (const float*)d_in[4];
    const float* b1    = (const float*)d_in[5];
    const float* w2    = (const float*)d_in[6];
    const float* b2    = (const float*)d_in[7];
    const float* mw1   = (const float*)d_in[8];
    const float* mb1   = (const float*)d_in[9];
    const float* mw2   = (const float*)d_in[10];
    const float* mb2   = (const float*)d_in[11];
    float* out = (float*)d_out;

    cudaFuncSetAttribute(k_fused, cudaFuncAttributeMaxDynamicSharedMemorySize,
                         FSM_TOTAL);

    k_pre<<<Bb * 8 + 70, 320>>>(words, spos, opos, emb, w1);
    k_pools_fin<<<Bb, 320>>>();
    k_supproj<<<dim3(Bb, 6), 256>>>(w1);
    k_fused<<<dim3(Bb, 8), 256, FSM_TOTAL>>>(words, emb, w2, b2, b1);
    k_attn_part<<<dim3(Bb, 8), 640>>>(words, emb);
    k_mlp1<<<dim3(Bb, 8), 256>>>(mw1);
    k_mlp2<<<Bb, 256>>>(mb1, mw2, mb2, out);
}